// round 5
// baseline (speedup 1.0000x reference)
#include <cuda_runtime.h>
#include <cstdint>

#define NHEAD  16
#define LSEQ   2048
#define DMODEL 1024
#define DHEAD  64
#define NBATCH 2
#define MROWS  (NBATCH * LSEQ)   // 4096
#define NCOLS  (NHEAD * DHEAD)   // 1024

__device__ float g_qp[(size_t)NBATCH * NHEAD * LSEQ * DHEAD];
__device__ float g_kp[(size_t)NBATCH * NHEAD * LSEQ * DHEAD];
__device__ float g_vp[(size_t)NBATCH * NHEAD * LSEQ * DHEAD];
__device__ float g_gate[(size_t)MROWS * NCOLS];
__device__ float g_att[(size_t)MROWS * NCOLS];

__device__ __forceinline__ float tf32r(float x) {
    uint32_t u;
    asm("cvt.rna.tf32.f32 %0, %1;" : "=r"(u) : "f"(x));
    return __uint_as_float(u);
}
__device__ __forceinline__ void mma8(float* d,
                                     uint32_t a0, uint32_t a1, uint32_t a2, uint32_t a3,
                                     uint32_t b0, uint32_t b1) {
    asm volatile(
        "mma.sync.aligned.m16n8k8.row.col.f32.tf32.tf32.f32 "
        "{%0,%1,%2,%3}, {%4,%5,%6,%7}, {%8,%9}, {%0,%1,%2,%3};\n"
        : "+f"(d[0]), "+f"(d[1]), "+f"(d[2]), "+f"(d[3])
        : "r"(a0), "r"(a1), "r"(a2), "r"(a3), "r"(b0), "r"(b1));
}
__device__ __forceinline__ void cpa16(void* dst, const void* src) {
    uint32_t d = (uint32_t)__cvta_generic_to_shared(dst);
    asm volatile("cp.async.ca.shared.global [%0], [%1], 16;\n" :: "r"(d), "l"(src));
}
#define CP_COMMIT() asm volatile("cp.async.commit_group;\n")
#define CP_WAIT(N)  asm volatile("cp.async.wait_group %0;\n" :: "n"(N))

// ===== unified GEMM: C[4096,1024] = X[4096,1024]*W[1024,1024] =====
// mode: 0=q(scale,head-major) 1=k 2=v 3=gate(sigmoid+gbias) 4=oproj(+obias->out)
#define PA 20   // A pitch: banks (20g+t) all distinct
#define PB 72   // B pitch: banks (8t+g) all distinct
#define PST 3

__global__ __launch_bounds__(256)
void gemm_kernel(const float* __restrict__ X, const float* __restrict__ W,
                 const float* __restrict__ aux, float* __restrict__ out, int mode)
{
    __shared__ float As[PST][128 * PA];
    __shared__ float Bs[PST][16 * PB];

    const int row0 = blockIdx.y * 128;
    const int col0 = blockIdx.x * 64;
    const int tid  = threadIdx.x;
    const int lane = tid & 31, wid = tid >> 5;
    const int g = lane >> 2, t = lane & 3;
    const int warp_m = wid & 3, warp_n = wid >> 2;

    float acc[2][4][4];
#pragma unroll
    for (int mt = 0; mt < 2; ++mt)
#pragma unroll
        for (int nt = 0; nt < 4; ++nt)
#pragma unroll
            for (int e = 0; e < 4; ++e) acc[mt][nt][e] = 0.f;

    const int ar = tid >> 2, akq = (tid & 3) << 2;          // A: rows 0..63 (+64)
    const int bk = tid >> 4, bnq = (tid & 15) << 2;         // B: 16x64

    auto issue = [&](int kt) {
        int s = kt % PST, k0 = kt * 16;
        cpa16(&As[s][ar * PA + akq],        &X[(size_t)(row0 + ar) * DMODEL + k0 + akq]);
        cpa16(&As[s][(ar + 64) * PA + akq], &X[(size_t)(row0 + ar + 64) * DMODEL + k0 + akq]);
        cpa16(&Bs[s][bk * PB + bnq],        &W[(size_t)(k0 + bk) * NCOLS + col0 + bnq]);
        CP_COMMIT();
    };
    issue(0); issue(1);

    const int r0 = warp_m * 32 + g;
    const int c0 = warp_n * 32 + g;

    for (int kt = 0; kt < 64; ++kt) {
        // pending groups at this point: {kt, kt+1} -> allow 1 outstanding so
        // tile kt is guaranteed complete (this was the round-4 bug: N=2).
        if (kt < 63) { CP_WAIT(1); } else { CP_WAIT(0); }
        __syncthreads();

        const float* as = As[kt % PST];
        const float* bs = Bs[kt % PST];
#pragma unroll
        for (int kc = 0; kc < 16; kc += 8) {
            uint32_t af[4][2], bf[4][2];
#pragma unroll
            for (int rr = 0; rr < 4; ++rr) {
                const float* ap = &as[(r0 + rr * 8) * PA + kc + t];
                af[rr][0] = __float_as_uint(tf32r(ap[0]));
                af[rr][1] = __float_as_uint(tf32r(ap[4]));
            }
#pragma unroll
            for (int nt = 0; nt < 4; ++nt) {
                const float* bp = &bs[(kc + t) * PB + c0 + nt * 8];
                bf[nt][0] = __float_as_uint(tf32r(bp[0]));
                bf[nt][1] = __float_as_uint(tf32r(bp[4 * PB]));
            }
#pragma unroll
            for (int mt = 0; mt < 2; ++mt)
#pragma unroll
                for (int nt = 0; nt < 4; ++nt)
                    mma8(acc[mt][nt],
                         af[mt*2][0], af[mt*2+1][0], af[mt*2][1], af[mt*2+1][1],
                         bf[nt][0], bf[nt][1]);
        }
        __syncthreads();
        if (kt + 2 < 64) issue(kt + 2);
    }

#pragma unroll
    for (int mt = 0; mt < 2; ++mt)
#pragma unroll
        for (int nt = 0; nt < 4; ++nt) {
            int rg0 = row0 + warp_m * 32 + mt * 16 + g;
            int cg  = col0 + warp_n * 32 + nt * 8 + 2 * t;
            int rr[4] = {rg0, rg0, rg0 + 8, rg0 + 8};
            int cc[4] = {cg, cg + 1, cg, cg + 1};
#pragma unroll
            for (int e = 0; e < 4; ++e) {
                int row = rr[e], col = cc[e];
                float v = acc[mt][nt][e];
                if (mode <= 2) {
                    if (mode == 0) v *= 0.125f;
                    int bb = row >> 11, l = row & (LSEQ - 1);
                    int hh = col >> 6,  cx = col & (DHEAD - 1);
                    float* dst = (mode == 0) ? g_qp : ((mode == 1) ? g_kp : g_vp);
                    dst[((((size_t)bb * NHEAD + hh) * LSEQ) + l) * DHEAD + cx] = tf32r(v);
                } else if (mode == 3) {
                    float xg = v + aux[col];
                    g_gate[(size_t)row * NCOLS + col] = 1.f / (1.f + __expf(-xg));
                } else {
                    out[(size_t)row * DMODEL + col] = v + aux[col];
                }
            }
        }
}

// ===== Flash attention =====
#define BQ   128
#define BKT  64
#define QP   68   // [row][c]  A operand, banks 4g+t
#define KP   68   // [kk][c]   B operand (n on pitch), banks 4g+t
#define VP   72   // [kk][c]   B operand (k on pitch), banks 8t+g
#define SP2  68   // [row][kk] S/P
#define ATTN_SMEM_FLOATS (BQ*QP + BKT*KP + BKT*VP + BQ*SP2 + 3*BQ)
#define ATTN_SMEM_BYTES  (ATTN_SMEM_FLOATS * 4)

__global__ __launch_bounds__(256, 2)
void attn_kernel(const float* __restrict__ bias, const int* __restrict__ mask)
{
    extern __shared__ float sm[];
    float* q_s   = sm;
    float* k_s   = q_s + BQ * QP;
    float* v_s   = k_s + BKT * KP;
    float* s_s   = v_s + BKT * VP;
    float* m_sm  = s_s + BQ * SP2;
    float* l_sm  = m_sm + BQ;
    float* al_sm = l_sm + BQ;

    const int b = blockIdx.z, h = blockIdx.y;
    const int q0 = blockIdx.x * BQ;
    const int tid = threadIdx.x;
    const int lane = tid & 31, wid = tid >> 5;
    const int g = lane >> 2, t = lane & 3;
    const int warp_m = wid & 3, warp_n = wid >> 2;
    const float LOG2E = 1.4426950408889634f;

    // async q tile (128x64, pre-scaled + tf32-rounded)
    const float* qbase = g_qp + (((size_t)b * NHEAD + h) * LSEQ + q0) * DHEAD;
#pragma unroll
    for (int i = 0; i < 8; ++i) {
        int idx = tid + i * 256;
        int r = idx >> 4, cq = (idx & 15) << 2;
        cpa16(&q_s[r * QP + cq], &qbase[(size_t)r * DHEAD + cq]);
    }
    CP_COMMIT();
    if (tid < BQ) { m_sm[tid] = -1e30f; l_sm[tid] = 0.f; }

    float acc[2][4][4];
#pragma unroll
    for (int mt = 0; mt < 2; ++mt)
#pragma unroll
        for (int nt = 0; nt < 4; ++nt)
#pragma unroll
            for (int e = 0; e < 4; ++e) acc[mt][nt][e] = 0.f;

    const int r0 = warp_m * 32 + g;
    const int c0 = warp_n * 32 + g;
    const int sr = tid >> 1, hf = tid & 1;
    const int kvr = tid >> 2, kvc = (tid & 3) << 2;    // 64 rows x 4 col-chunks

    for (int kt = 0; kt < LSEQ / BKT; ++kt) {
        __syncthreads();                 // prior tile fully consumed
        const int k0 = kt * BKT;
        const float* kb = g_kp + (((size_t)b * NHEAD + h) * LSEQ + k0) * DHEAD;
        const float* vb = g_vp + (((size_t)b * NHEAD + h) * LSEQ + k0) * DHEAD;
#pragma unroll
        for (int i = 0; i < 4; ++i) {
            cpa16(&k_s[kvr * KP + kvc + 16 * i], &kb[(size_t)kvr * DHEAD + kvc + 16 * i]);
            cpa16(&v_s[kvr * VP + kvc + 16 * i], &vb[(size_t)kvr * DHEAD + kvc + 16 * i]);
        }
        CP_COMMIT();

        // overlap: bias -> regs, mask -> 1 packed bit-reg
        size_t off = (((size_t)b * NHEAD + h) * LSEQ + (q0 + sr)) * (size_t)LSEQ
                     + k0 + hf * 32;
        float4 bv[8];
        const float4* bp = reinterpret_cast<const float4*>(bias + off);
#pragma unroll
        for (int j = 0; j < 8; ++j) bv[j] = __ldcs(bp + j);
        uint32_t mb = 0;
        const int4* mp = reinterpret_cast<const int4*>(mask + off);
#pragma unroll
        for (int j4 = 0; j4 < 8; ++j4) {
            int4 mi = __ldcs(mp + j4);
            mb |= (mi.x ? 1u : 0u) << (j4 * 4);
            mb |= (mi.y ? 1u : 0u) << (j4 * 4 + 1);
            mb |= (mi.z ? 1u : 0u) << (j4 * 4 + 2);
            mb |= (mi.w ? 1u : 0u) << (j4 * 4 + 3);
        }
        CP_WAIT(0);
        __syncthreads();

        // ---- S = q * k^T ----
        float sacc[2][4][4];
#pragma unroll
        for (int mt = 0; mt < 2; ++mt)
#pragma unroll
            for (int nt = 0; nt < 4; ++nt)
#pragma unroll
                for (int e = 0; e < 4; ++e) sacc[mt][nt][e] = 0.f;
#pragma unroll
        for (int kc = 0; kc < DHEAD; kc += 8) {
            uint32_t af[4][2], bf[4][2];
#pragma unroll
            for (int rr = 0; rr < 4; ++rr) {
                const float* ap = &q_s[(r0 + rr * 8) * QP + kc + t];
                af[rr][0] = __float_as_uint(ap[0]);
                af[rr][1] = __float_as_uint(ap[4]);
            }
#pragma unroll
            for (int nt = 0; nt < 4; ++nt) {
                const float* kp = &k_s[(c0 + nt * 8) * KP + kc + t];
                bf[nt][0] = __float_as_uint(kp[0]);
                bf[nt][1] = __float_as_uint(kp[4]);
            }
#pragma unroll
            for (int mt = 0; mt < 2; ++mt)
#pragma unroll
                for (int nt = 0; nt < 4; ++nt)
                    mma8(sacc[mt][nt],
                         af[mt*2][0], af[mt*2+1][0], af[mt*2][1], af[mt*2+1][1],
                         bf[nt][0], bf[nt][1]);
        }
#pragma unroll
        for (int mt = 0; mt < 2; ++mt) {
            int rb = warp_m * 32 + mt * 16;
#pragma unroll
            for (int nt = 0; nt < 4; ++nt) {
                int cb = warp_n * 32 + nt * 8;
                s_s[(rb + g) * SP2 + cb + 2*t]       = sacc[mt][nt][0];
                s_s[(rb + g) * SP2 + cb + 2*t + 1]   = sacc[mt][nt][1];
                s_s[(rb + 8 + g) * SP2 + cb + 2*t]   = sacc[mt][nt][2];
                s_s[(rb + 8 + g) * SP2 + cb + 2*t+1] = sacc[mt][nt][3];
            }
        }
        __syncthreads();

        // ---- bias + online softmax (full-row denom) + post-softmax mask ----
        {
            float f[32], mx = -1e30f;
#pragma unroll
            for (int j = 0; j < 8; ++j) {
                int c = hf * 32 + j * 4;
                f[j*4+0] = s_s[sr * SP2 + c + 0] + bv[j].x;
                f[j*4+1] = s_s[sr * SP2 + c + 1] + bv[j].y;
                f[j*4+2] = s_s[sr * SP2 + c + 2] + bv[j].z;
                f[j*4+3] = s_s[sr * SP2 + c + 3] + bv[j].w;
                mx = fmaxf(mx, fmaxf(fmaxf(f[j*4], f[j*4+1]), fmaxf(f[j*4+2], f[j*4+3])));
            }
            mx = fmaxf(mx, __shfl_xor_sync(0xffffffffu, mx, 1));
            float m_old = m_sm[sr];
            float m_new = fmaxf(m_old, mx);
            float alpha = exp2f((m_old - m_new) * LOG2E);

            float lsum = 0.f;
            float4* prow = reinterpret_cast<float4*>(&s_s[sr * SP2 + hf * 32]);
#pragma unroll
            for (int j4 = 0; j4 < 8; ++j4) {
                float p0 = exp2f((f[j4*4+0] - m_new) * LOG2E);
                float p1 = exp2f((f[j4*4+1] - m_new) * LOG2E);
                float p2 = exp2f((f[j4*4+2] - m_new) * LOG2E);
                float p3 = exp2f((f[j4*4+3] - m_new) * LOG2E);
                lsum += (p0 + p1) + (p2 + p3);
                float4 pv;
                pv.x = tf32r((mb >> (j4*4+0)) & 1u ? p0 : 0.f);
                pv.y = tf32r((mb >> (j4*4+1)) & 1u ? p1 : 0.f);
                pv.z = tf32r((mb >> (j4*4+2)) & 1u ? p2 : 0.f);
                pv.w = tf32r((mb >> (j4*4+3)) & 1u ? p3 : 0.f);
                prow[j4] = pv;
            }
            lsum += __shfl_xor_sync(0xffffffffu, lsum, 1);
            if (hf == 0) {
                l_sm[sr] = l_sm[sr] * alpha + lsum;
                m_sm[sr] = m_new;
                al_sm[sr] = alpha;
            }
        }
        __syncthreads();

        // ---- rescale acc; acc += P * V ----
#pragma unroll
        for (int mt = 0; mt < 2; ++mt) {
            int rb = warp_m * 32 + mt * 16;
            float a0 = al_sm[rb + g], a1 = al_sm[rb + 8 + g];
#pragma unroll
            for (int nt = 0; nt < 4; ++nt) {
                acc[mt][nt][0] *= a0; acc[mt][nt][1] *= a0;
                acc[mt][nt][2] *= a1; acc[mt][nt][3] *= a1;
            }
        }
#pragma unroll
        for (int kc = 0; kc < BKT; kc += 8) {
            uint32_t af[4][2], bf[4][2];
#pragma unroll
            for (int rr = 0; rr < 4; ++rr) {
                const float* ap = &s_s[(r0 + rr * 8) * SP2 + kc + t];
                af[rr][0] = __float_as_uint(ap[0]);
                af[rr][1] = __float_as_uint(ap[4]);
            }
#pragma unroll
            for (int nt = 0; nt < 4; ++nt) {
                const float* vp = &v_s[(kc + t) * VP + c0 + nt * 8];
                bf[nt][0] = __float_as_uint(vp[0]);
                bf[nt][1] = __float_as_uint(vp[4 * VP]);
            }
#pragma unroll
            for (int mt = 0; mt < 2; ++mt)
#pragma unroll
                for (int nt = 0; nt < 4; ++nt)
                    mma8(acc[mt][nt],
                         af[mt*2][0], af[mt*2+1][0], af[mt*2][1], af[mt*2+1][1],
                         bf[nt][0], bf[nt][1]);
        }
    }

    // ---- epilogue: /l, *gate ----
#pragma unroll
    for (int mt = 0; mt < 2; ++mt)
#pragma unroll
        for (int nt = 0; nt < 4; ++nt) {
            int rl0 = warp_m * 32 + mt * 16 + g;
            int cb  = warp_n * 32 + nt * 8 + 2 * t;
            float inv0 = 1.f / l_sm[rl0];
            float inv1 = 1.f / l_sm[rl0 + 8];
            size_t base0 = ((size_t)(b * LSEQ + q0 + rl0)) * NCOLS + h * DHEAD;
            size_t base1 = ((size_t)(b * LSEQ + q0 + rl0 + 8)) * NCOLS + h * DHEAD;
            g_att[base0 + cb]     = acc[mt][nt][0] * inv0 * g_gate[base0 + cb];
            g_att[base0 + cb + 1] = acc[mt][nt][1] * inv0 * g_gate[base0 + cb + 1];
            g_att[base1 + cb]     = acc[mt][nt][2] * inv1 * g_gate[base1 + cb];
            g_att[base1 + cb + 1] = acc[mt][nt][3] * inv1 * g_gate[base1 + cb + 1];
        }
}

// ===== launcher =====
extern "C" void kernel_launch(void* const* d_in, const int* in_sizes, int n_in,
                              void* d_out, int out_size)
{
    const float* Q    = (const float*)d_in[0];
    const float* K    = (const float*)d_in[1];
    const float* V    = (const float*)d_in[2];
    const float* bias = (const float*)d_in[3];
    const int*   mask = (const int*)d_in[4];
    const float* qw   = (const float*)d_in[5];
    const float* kw   = (const float*)d_in[6];
    const float* vw   = (const float*)d_in[7];
    const float* gw   = (const float*)d_in[8];
    const float* gb   = (const float*)d_in[9];
    const float* ow   = (const float*)d_in[10];
    const float* ob   = (const float*)d_in[11];
    float* out = (float*)d_out;

    static float* g_att_p = nullptr;
    if (!g_att_p) cudaGetSymbolAddress((void**)&g_att_p, g_att);

    cudaFuncSetAttribute(attn_kernel, cudaFuncAttributeMaxDynamicSharedMemorySize,
                         ATTN_SMEM_BYTES);

    dim3 gg(NCOLS / 64, MROWS / 128);          // 16 x 32
    gemm_kernel<<<gg, 256>>>(Q, qw, nullptr, nullptr, 0);
    gemm_kernel<<<gg, 256>>>(K, kw, nullptr, nullptr, 1);
    gemm_kernel<<<gg, 256>>>(V, vw, nullptr, nullptr, 2);
    gemm_kernel<<<gg, 256>>>(Q, gw, gb, nullptr, 3);

    dim3 ga(LSEQ / BQ, NHEAD, NBATCH);         // 16 x 16 x 2
    attn_kernel<<<ga, 256, ATTN_SMEM_BYTES>>>(bias, mask);

    gemm_kernel<<<gg, 256>>>(g_att_p, ow, ob, out, 4);
}